// round 11
// baseline (speedup 1.0000x reference)
#include <cuda_runtime.h>
#include <math_constants.h>
#include <stdint.h>

#define NROWS 8192      // B*M
#define VSZ   5003
#define NB    64
#define SSEQ  200
#define DDIM  128
#define NNEG  4
#define MAXA  8
#define INV_TAU (1.0f/0.07f)
#define KS    16         // dims per k-slice
#define NSL   (DDIM/KS)  // 8 slices
#define NCON  (NB*NNEG)  // 256 contrast blocks
#define GRID  (NCON + NROWS)   // 8448 == 33 * 256 exactly
#define STRIDE 33        // contrast block every 33rd id -> spread across waves
#define NEGSENT (-1e30f)

// deterministic scratch (single int counter atomic; no float atomics)
__device__ float g_fl[NROWS];
__device__ float g_cnt[NROWS];
__device__ int   g_na[NB];
__device__ float g_pm[NB][NNEG][MAXA];
__device__ float g_psum[NB][NNEG][MAXA];
__device__ float g_possim[NB][MAXA];
__device__ int   g_ctr = 0;          // last-block-done counter (self-resetting)

struct ConSmem {
    float anch[MAXA][DDIM];          // normalized anchors       4 KB
    float tile[SSEQ][KS + 4];        // raw negative k-slice    16 KB
    float pm[8][MAXA], ps[8][MAXA];
    int   sel[16];
    int   na;
    unsigned char v[SSEQ], nv[SSEQ];
};

__global__ __launch_bounds__(256) void mega_kernel(
    const float* __restrict__ logits,
    const int*   __restrict__ targets,
    const int*   __restrict__ mask,
    const float* __restrict__ emb,
    const int*   __restrict__ pids,
    const int*   __restrict__ amask,
    float* __restrict__ out)
{
    __shared__ __align__(16) char sm_raw[sizeof(ConSmem)];
    int tid = threadIdx.x, lane = tid & 31, w = tid >> 5;
    int bid = blockIdx.x;
    bool is_con = (bid % STRIDE) == 0;   // 256 contrast blocks spread through grid

    if (is_con) {
        // ================= contrast block (b, j) — fully self-prepped ======
        ConSmem* S = (ConSmem*)sm_raw;
        int blk = bid / STRIDE;          // 0..255
        int b = blk >> 2, j = blk & 3;
        int nb = j + (j >= b ? 1 : 0);   // others[b][j]

        if (tid < SSEQ) {
            S->v[tid]  = (amask[b  * SSEQ + tid] == 1 && pids[b  * SSEQ + tid] > 0) ? 1 : 0;
            S->nv[tid] = (amask[nb * SSEQ + tid] == 1 && pids[nb * SSEQ + tid] > 0) ? 1 : 0;
        }
        __syncthreads();
        if (tid == 0) {
            int first16[16];
            #pragma unroll
            for (int i = 0; i < 16; i++) first16[i] = 0;
            int n = 0;
            for (int s = 0; s < SSEQ; s++) if (S->v[s]) { if (n < 16) first16[n] = s; n++; }
            int na = n / 2; if (na > MAXA) na = MAXA;
            S->na = na;
            #pragma unroll
            for (int i = 0; i < 16; i++) S->sel[i] = first16[i];
        }
        __syncthreads();
        int na = S->na;

        // warp w: load + normalize anchor w (unused anchors -> garbage, masked)
        {
            int ai = S->sel[w];
            float4 a4 = ((const float4*)(emb + ((size_t)b * SSEQ + ai) * DDIM))[lane];
            float n2 = a4.x * a4.x + a4.y * a4.y + a4.z * a4.z + a4.w * a4.w;
            #pragma unroll
            for (int o = 16; o; o >>= 1) n2 += __shfl_xor_sync(0xffffffffu, n2, o);
            float inv = 1.0f / fmaxf(sqrtf(n2), 1e-12f);
            a4.x *= inv; a4.y *= inv; a4.z *= inv; a4.w *= inv;
            ((float4*)S->anch[w])[lane] = a4;
        }

        // positive similarity (j==0): warp w -> anchor w (needs anch[w] only)
        if (j == 0 && w < na) {
            int pi = S->sel[na + w];
            float4 p = ((const float4*)(emb + ((size_t)b * SSEQ + pi) * DDIM))[lane];
            float4 a4 = ((const float4*)S->anch[w])[lane];
            float d  = a4.x * p.x + a4.y * p.y + a4.z * p.z + a4.w * p.w;
            float pn = p.x * p.x + p.y * p.y + p.z * p.z + p.w * p.w;
            #pragma unroll
            for (int o = 16; o; o >>= 1) {
                d  += __shfl_xor_sync(0xffffffffu, d,  o);
                pn += __shfl_xor_sync(0xffffffffu, pn, o);
            }
            if (lane == 0)
                g_possim[b][w] = d * (1.0f / fmaxf(sqrtf(pn), 1e-12f)) * INV_TAU;
        }

        // negatives: thread owns negative tid (<200); raw dot + |n|^2 per slice
        const float* nbase = emb + (size_t)nb * SSEQ * DDIM;
        int nc = (tid < SSEQ) ? tid : (SSEQ - 1);
        float acc[MAXA], nn2 = 0.f;
        #pragma unroll
        for (int a = 0; a < MAXA; a++) acc[a] = 0.f;

        for (int sl = 0; sl < NSL; sl++) {
            __syncthreads();                 // prev slice consumed / anchors ready
            for (int q = tid; q < SSEQ * 4; q += 256) {
                int rowi = q >> 2, col = q & 3;
                *(float4*)&S->tile[rowi][col * 4] =
                    ((const float4*)(nbase + (size_t)rowi * DDIM + sl * KS))[col];
            }
            __syncthreads();
            #pragma unroll
            for (int c = 0; c < 4; c++) {
                float4 ng = *(const float4*)&S->tile[nc][c * 4];     // conflict-free
                nn2 += ng.x * ng.x + ng.y * ng.y + ng.z * ng.z + ng.w * ng.w;
                #pragma unroll
                for (int a = 0; a < MAXA; a++) {
                    float4 av = *(const float4*)&S->anch[a][sl * KS + c * 4]; // broadcast
                    acc[a] += av.x * ng.x + av.y * ng.y + av.z * ng.z + av.w * ng.w;
                }
            }
        }

        float sc = (1.0f / fmaxf(sqrtf(nn2), 1e-12f)) * INV_TAU;
        bool valid = (tid < SSEQ) && S->nv[tid];
        #pragma unroll
        for (int a = 0; a < MAXA; a++) {
            float sim = valid ? acc[a] * sc : NEGSENT;
            float mv = sim;
            #pragma unroll
            for (int o = 16; o; o >>= 1) mv = fmaxf(mv, __shfl_xor_sync(0xffffffffu, mv, o));
            float e = __expf(sim - mv);      // all-invalid warp washes out in merge
            #pragma unroll
            for (int o = 16; o; o >>= 1) e += __shfl_xor_sync(0xffffffffu, e, o);
            if (lane == 0) { S->pm[w][a] = mv; S->ps[w][a] = e; }
        }
        __syncthreads();
        if (tid < MAXA) {                    // thread a merges 8 warp partials
            float M = NEGSENT, Sm = 0.f;
            #pragma unroll
            for (int ww = 0; ww < 8; ww++) {
                float pm = S->pm[ww][tid], ps = S->ps[ww][tid];
                float nm = fmaxf(M, pm);
                Sm = Sm * __expf(M - nm) + ps * __expf(pm - nm);
                M = nm;
            }
            g_pm[b][j][tid] = M; g_psum[b][j][tid] = Sm;
        }
        if (j == 0 && tid == 0) g_na[b] = na;
    } else {
        // ================= focal row (one-pass, no-max — R7 winner) ========
        int r = bid - bid / STRIDE - 1;      // skip the interleaved contrast ids
        int t = targets[r];
        bool valid = (t != -100) && (mask[r] == 1);
        if (!valid) {
            if (tid == 0) { g_fl[r] = 0.f; g_cnt[r] = 0.f; }
        } else {
            const float* row = logits + (size_t)r * VSZ;
            float lt = __ldg(row + t);
            int pre = (4 - (int)(((uintptr_t)row >> 2) & 3)) & 3;
            const float4* rv = (const float4*)(row + pre);
            int nv = (VSZ - pre) >> 2;
            int tail = pre + (nv << 2);

            float s = 0.f;
            if (tid < pre) s += __expf(row[tid]);
            for (int i = tid; i < nv; i += 256) {
                float4 x = rv[i];
                s += __expf(x.x) + __expf(x.y) + __expf(x.z) + __expf(x.w);
            }
            for (int i = tail + tid; i < VSZ; i += 256) s += __expf(row[i]);

            #pragma unroll
            for (int o = 16; o; o >>= 1) s += __shfl_xor_sync(0xffffffffu, s, o);
            float* ss = (float*)sm_raw;
            if (lane == 0) ss[w] = s;
            __syncthreads();
            if (tid == 0) {
                float S = 0.f;
                #pragma unroll
                for (int i = 0; i < 8; i++) S += ss[i];
                float lp = lt - logf(S);
                float pt = __expf(lp);
                float om = 1.f - pt;
                g_fl[r] = om * om * (-lp);
                g_cnt[r] = 1.f;
            }
        }
    }

    // ================= last-block-done finalize (deterministic) ============
    __threadfence();
    __shared__ int s_last;
    if (tid == 0) {
        int vdone = atomicAdd(&g_ctr, 1);
        s_last = (vdone == GRID - 1) ? 1 : 0;
    }
    __syncthreads();
    if (!s_last) return;

    // reduce g_fl / g_cnt (L2-hot, coalesced float4)
    float fs = 0.f, cnt = 0.f;
    const float4* fv = (const float4*)g_fl;
    const float4* cv = (const float4*)g_cnt;
    for (int q = tid; q < NROWS / 4; q += 256) {
        float4 f = fv[q], c = cv[q];
        fs  += (f.x + f.y) + (f.z + f.w);
        cnt += (c.x + c.y) + (c.z + c.w);
    }

    float closs = 0.f;
    #pragma unroll
    for (int rep = 0; rep < 2; rep++) {
        int idx = tid + rep * 256;
        int b = idx >> 3, aq = idx & 7;
        int na = g_na[b];
        float ps = g_possim[b][aq];
        float m = ps, ssum = 1.f;
        #pragma unroll
        for (int jj = 0; jj < NNEG; jj++) {
            float pm  = g_pm[b][jj][aq];
            float pss = g_psum[b][jj][aq];
            if (pss > 0.f) {
                float nm = fmaxf(m, pm);
                ssum = ssum * __expf(m - nm) + pss * __expf(pm - nm);
                m = nm;
            }
        }
        closs += (aq < na) ? ((m + logf(ssum)) - ps) : 0.f;
    }
    float pairs = (tid < NB) ? (float)g_na[tid] : 0.f;

    #pragma unroll
    for (int o = 16; o; o >>= 1) {
        fs    += __shfl_xor_sync(0xffffffffu, fs,    o);
        cnt   += __shfl_xor_sync(0xffffffffu, cnt,   o);
        closs += __shfl_xor_sync(0xffffffffu, closs, o);
        pairs += __shfl_xor_sync(0xffffffffu, pairs, o);
    }
    __shared__ float4 sred[8];
    if (lane == 0) sred[w] = make_float4(fs, cnt, closs, pairs);
    __syncthreads();
    if (tid == 0) {
        float F = 0.f, C = 0.f, L = 0.f, P = 0.f;
        #pragma unroll
        for (int i = 0; i < 8; i++) {
            float4 q = sred[i];
            F += q.x; C += q.y; L += q.z; P += q.w;
        }
        float focal = C > 0.f ? F / C : 0.f;
        float contr = P > 0.f ? L / P : 0.f;
        out[0] = 0.6f * focal + 0.2f * contr;
        g_ctr = 0;                           // reset for next graph replay
    }
}

extern "C" void kernel_launch(void* const* d_in, const int* in_sizes, int n_in,
                              void* d_out, int out_size)
{
    const float* logits  = (const float*)d_in[0];
    const int*   targets = (const int*)d_in[1];
    const int*   mask    = (const int*)d_in[2];
    const float* emb     = (const float*)d_in[3];
    const int*   pids    = (const int*)d_in[4];
    const int*   amask   = (const int*)d_in[5];
    float* out = (float*)d_out;

    mega_kernel<<<GRID, 256>>>(logits, targets, mask, emb, pids, amask, out);
}

// round 12
// speedup vs baseline: 1.5057x; 1.5057x over previous
#include <cuda_runtime.h>
#include <math_constants.h>
#include <stdint.h>

#define NROWS 8192      // B*M
#define VSZ   5003
#define NB    64
#define SSEQ  200
#define DDIM  128
#define NNEG  4
#define MAXA  8
#define INV_TAU (1.0f/0.07f)
#define KS    16         // dims per k-slice
#define NSL   (DDIM/KS)  // 8 slices
#define NCON  (NB*NNEG)  // 256 contrast blocks
#define NRED  32         // fl-reduce blocks (256 rows each)
#define SGRID (NCON + NRED)
#define NEGSENT (-1e30f)

// deterministic scratch (single int counter atomic; no float atomics)
__device__ float g_fl[NROWS];
__device__ float g_pfl[NRED];
__device__ float g_pcnt[NRED];
__device__ int   g_na[NB];
__device__ float g_pm[NB][NNEG][MAXA];
__device__ float g_psum[NB][NNEG][MAXA];
__device__ float g_possim[NB][MAXA];
__device__ int   g_ctr = 0;          // last-block-done counter (self-resetting)

// ================= primary: focal (one-pass, no-max — measured best) =======
__global__ __launch_bounds__(256) void focal_kernel(
    const float* __restrict__ logits,
    const int*   __restrict__ targets,
    const int*   __restrict__ mask)
{
#if __CUDA_ARCH__ >= 900
    cudaTriggerProgrammaticLaunchCompletion();   // let secondary launch early
#endif
    int r = blockIdx.x;
    int tid = threadIdx.x, lane = tid & 31, w = tid >> 5;
    int t = targets[r];
    bool valid = (t != -100) && (mask[r] == 1);
    if (!valid) {
        if (tid == 0) g_fl[r] = 0.f;
        return;
    }
    const float* row = logits + (size_t)r * VSZ;
    float lt = __ldg(row + t);                               // target logit
    int pre = (4 - (int)(((uintptr_t)row >> 2) & 3)) & 3;    // peel to 16B align
    const float4* rv = (const float4*)(row + pre);
    int nv = (VSZ - pre) >> 2;
    int tail = pre + (nv << 2);

    float s = 0.f;
    if (tid < pre) s += __expf(row[tid]);
    for (int i = tid; i < nv; i += 256) {
        float4 x = rv[i];
        s += __expf(x.x) + __expf(x.y) + __expf(x.z) + __expf(x.w);
    }
    for (int i = tail + tid; i < VSZ; i += 256) s += __expf(row[i]);

    #pragma unroll
    for (int o = 16; o; o >>= 1) s += __shfl_xor_sync(0xffffffffu, s, o);
    __shared__ float ss[8];
    if (lane == 0) ss[w] = s;
    __syncthreads();
    if (tid == 0) {
        float S = 0.f;
        #pragma unroll
        for (int i = 0; i < 8; i++) S += ss[i];
        float lp = lt - logf(S);          // log p_t
        float pt = __expf(lp);
        float om = 1.f - pt;
        g_fl[r] = om * om * (-lp);
    }
}

// ======= secondary (PDL): contrast (self-prepped, blocks 0..255) +
//         fl-reduce (blocks 256..287, waits on primary) + finalize ==========
struct ConSmem {
    float anch[MAXA][DDIM];          // normalized anchors       4 KB
    float tile[SSEQ][KS + 4];        // raw negative k-slice    16 KB
    float pm[8][MAXA], ps[8][MAXA];
    int   sel[16];
    int   na;
    unsigned char v[SSEQ], nv[SSEQ];
};

__global__ __launch_bounds__(256) void contrast_kernel(
    const float* __restrict__ emb,
    const int*   __restrict__ pids,
    const int*   __restrict__ amask,
    const int*   __restrict__ targets,
    const int*   __restrict__ mask,
    float* __restrict__ out)
{
    __shared__ __align__(16) char sm_raw[sizeof(ConSmem)];
    int tid = threadIdx.x, lane = tid & 31, w = tid >> 5;
    int blk = blockIdx.x;

    if (blk >= NCON) {
        // ---- fl partial reduction: must wait for primary (focal) ----
#if __CUDA_ARCH__ >= 900
        cudaGridDependencySynchronize();
#endif
        int k = blk - NCON;
        int r = k * 256 + tid;
        float f = g_fl[r];
        int tt = targets[r];
        float c = ((tt != -100) && (mask[r] == 1)) ? 1.f : 0.f;
        #pragma unroll
        for (int o = 16; o; o >>= 1) {
            f += __shfl_xor_sync(0xffffffffu, f, o);
            c += __shfl_xor_sync(0xffffffffu, c, o);
        }
        float* sf = (float*)sm_raw;          // 8 + 8 floats
        float* sc = sf + 8;
        if (lane == 0) { sf[w] = f; sc[w] = c; }
        __syncthreads();
        if (tid == 0) {
            float F = 0.f, C = 0.f;
            #pragma unroll
            for (int i = 0; i < 8; i++) { F += sf[i]; C += sc[i]; }
            g_pfl[k] = F; g_pcnt[k] = C;
        }
    } else {
        // ---- contrast (b, j): self-prepped from raw emb (no focal dep) ----
        ConSmem* S = (ConSmem*)sm_raw;
        int b = blk >> 2, j = blk & 3;
        int nb = j + (j >= b ? 1 : 0);       // others[b][j]

        if (tid < SSEQ) {
            S->v[tid]  = (amask[b  * SSEQ + tid] == 1 && pids[b  * SSEQ + tid] > 0) ? 1 : 0;
            S->nv[tid] = (amask[nb * SSEQ + tid] == 1 && pids[nb * SSEQ + tid] > 0) ? 1 : 0;
        }
        __syncthreads();
        if (tid == 0) {
            int first16[16];
            #pragma unroll
            for (int i = 0; i < 16; i++) first16[i] = 0;
            int n = 0;
            for (int s = 0; s < SSEQ; s++) if (S->v[s]) { if (n < 16) first16[n] = s; n++; }
            int na = n / 2; if (na > MAXA) na = MAXA;
            S->na = na;
            #pragma unroll
            for (int i = 0; i < 16; i++) S->sel[i] = first16[i];
        }
        __syncthreads();
        int na = S->na;

        // warp w: load + normalize anchor w
        {
            int ai = S->sel[w];
            float4 a4 = ((const float4*)(emb + ((size_t)b * SSEQ + ai) * DDIM))[lane];
            float n2 = a4.x * a4.x + a4.y * a4.y + a4.z * a4.z + a4.w * a4.w;
            #pragma unroll
            for (int o = 16; o; o >>= 1) n2 += __shfl_xor_sync(0xffffffffu, n2, o);
            float inv = 1.0f / fmaxf(sqrtf(n2), 1e-12f);
            a4.x *= inv; a4.y *= inv; a4.z *= inv; a4.w *= inv;
            ((float4*)S->anch[w])[lane] = a4;
        }

        // positive similarity (j==0): warp w -> anchor w
        if (j == 0 && w < na) {
            int pi = S->sel[na + w];
            float4 p = ((const float4*)(emb + ((size_t)b * SSEQ + pi) * DDIM))[lane];
            float4 a4 = ((const float4*)S->anch[w])[lane];
            float d  = a4.x * p.x + a4.y * p.y + a4.z * p.z + a4.w * p.w;
            float pn = p.x * p.x + p.y * p.y + p.z * p.z + p.w * p.w;
            #pragma unroll
            for (int o = 16; o; o >>= 1) {
                d  += __shfl_xor_sync(0xffffffffu, d,  o);
                pn += __shfl_xor_sync(0xffffffffu, pn, o);
            }
            if (lane == 0)
                g_possim[b][w] = d * (1.0f / fmaxf(sqrtf(pn), 1e-12f)) * INV_TAU;
        }

        // negatives: thread owns negative tid (<200); dot + |n|^2 per slice
        const float* nbase = emb + (size_t)nb * SSEQ * DDIM;
        int nc = (tid < SSEQ) ? tid : (SSEQ - 1);
        float acc[MAXA], nn2 = 0.f;
        #pragma unroll
        for (int a = 0; a < MAXA; a++) acc[a] = 0.f;

        for (int sl = 0; sl < NSL; sl++) {
            __syncthreads();                 // prev slice consumed / anchors ready
            for (int q = tid; q < SSEQ * 4; q += 256) {
                int rowi = q >> 2, col = q & 3;
                *(float4*)&S->tile[rowi][col * 4] =
                    ((const float4*)(nbase + (size_t)rowi * DDIM + sl * KS))[col];
            }
            __syncthreads();
            #pragma unroll
            for (int c = 0; c < 4; c++) {
                float4 ng = *(const float4*)&S->tile[nc][c * 4];     // conflict-free
                nn2 += ng.x * ng.x + ng.y * ng.y + ng.z * ng.z + ng.w * ng.w;
                #pragma unroll
                for (int a = 0; a < MAXA; a++) {
                    float4 av = *(const float4*)&S->anch[a][sl * KS + c * 4]; // broadcast
                    acc[a] += av.x * ng.x + av.y * ng.y + av.z * ng.z + av.w * ng.w;
                }
            }
        }

        float sc2 = (1.0f / fmaxf(sqrtf(nn2), 1e-12f)) * INV_TAU;
        bool vld = (tid < SSEQ) && S->nv[tid];
        #pragma unroll
        for (int a = 0; a < MAXA; a++) {
            float sim = vld ? acc[a] * sc2 : NEGSENT;
            float mv = sim;
            #pragma unroll
            for (int o = 16; o; o >>= 1) mv = fmaxf(mv, __shfl_xor_sync(0xffffffffu, mv, o));
            float e = __expf(sim - mv);      // all-invalid warp washes out in merge
            #pragma unroll
            for (int o = 16; o; o >>= 1) e += __shfl_xor_sync(0xffffffffu, e, o);
            if (lane == 0) { S->pm[w][a] = mv; S->ps[w][a] = e; }
        }
        __syncthreads();
        if (tid < MAXA) {                    // thread a merges 8 warp partials
            float M = NEGSENT, Sm = 0.f;
            #pragma unroll
            for (int ww = 0; ww < 8; ww++) {
                float pm = S->pm[ww][tid], ps = S->ps[ww][tid];
                float nm = fmaxf(M, pm);
                Sm = Sm * __expf(M - nm) + ps * __expf(pm - nm);
                M = nm;
            }
            g_pm[b][j][tid] = M; g_psum[b][j][tid] = Sm;
        }
        if (j == 0 && tid == 0) g_na[b] = na;
    }

    // ================= last-block-done finalize (deterministic) ============
    __threadfence();
    __shared__ int s_last;
    if (tid == 0) {
        int vdone = atomicAdd(&g_ctr, 1);
        s_last = (vdone == SGRID - 1) ? 1 : 0;
    }
    __syncthreads();
    if (!s_last) return;

    float fs  = (tid < NRED) ? g_pfl[tid]  : 0.f;
    float cnt = (tid < NRED) ? g_pcnt[tid] : 0.f;

    float closs = 0.f;
    #pragma unroll
    for (int rep = 0; rep < 2; rep++) {
        int idx = tid + rep * 256;
        int b = idx >> 3, aq = idx & 7;
        int na = g_na[b];
        float ps = g_possim[b][aq];
        float m = ps, ssum = 1.f;
        #pragma unroll
        for (int jj = 0; jj < NNEG; jj++) {
            float pm  = g_pm[b][jj][aq];
            float pss = g_psum[b][jj][aq];
            if (pss > 0.f) {
                float nm = fmaxf(m, pm);
                ssum = ssum * __expf(m - nm) + pss * __expf(pm - nm);
                m = nm;
            }
        }
        closs += (aq < na) ? ((m + logf(ssum)) - ps) : 0.f;
    }
    float pairs = (tid < NB) ? (float)g_na[tid] : 0.f;

    #pragma unroll
    for (int o = 16; o; o >>= 1) {
        fs    += __shfl_xor_sync(0xffffffffu, fs,    o);
        cnt   += __shfl_xor_sync(0xffffffffu, cnt,   o);
        closs += __shfl_xor_sync(0xffffffffu, closs, o);
        pairs += __shfl_xor_sync(0xffffffffu, pairs, o);
    }
    __shared__ float4 sred[8];
    if (lane == 0) sred[w] = make_float4(fs, cnt, closs, pairs);
    __syncthreads();
    if (tid == 0) {
        float F = 0.f, C = 0.f, L = 0.f, P = 0.f;
        #pragma unroll
        for (int i = 0; i < 8; i++) {
            float4 q = sred[i];
            F += q.x; C += q.y; L += q.z; P += q.w;
        }
        float focal = C > 0.f ? F / C : 0.f;
        float contr = P > 0.f ? L / P : 0.f;
        out[0] = 0.6f * focal + 0.2f * contr;
        g_ctr = 0;                           // reset for next graph replay
    }
}

extern "C" void kernel_launch(void* const* d_in, const int* in_sizes, int n_in,
                              void* d_out, int out_size)
{
    const float* logits  = (const float*)d_in[0];
    const int*   targets = (const int*)d_in[1];
    const int*   mask    = (const int*)d_in[2];
    const float* emb     = (const float*)d_in[3];
    const int*   pids    = (const int*)d_in[4];
    const int*   amask   = (const int*)d_in[5];
    float* out = (float*)d_out;

    // primary
    focal_kernel<<<NROWS, 256>>>(logits, targets, mask);

    // secondary with Programmatic Dependent Launch: starts during focal's
    // drain; only fl-reduce blocks grid-dependency-synchronize on focal.
    cudaLaunchConfig_t cfg = {};
    cfg.gridDim  = dim3(SGRID, 1, 1);
    cfg.blockDim = dim3(256, 1, 1);
    cfg.dynamicSmemBytes = 0;
    cfg.stream = 0;                          // legacy default stream (captured)
    cudaLaunchAttribute attrs[1];
    attrs[0].id = cudaLaunchAttributeProgrammaticStreamSerialization;
    attrs[0].val.programmaticStreamSerializationAllowed = 1;
    cfg.attrs = attrs;
    cfg.numAttrs = 1;
    cudaLaunchKernelEx(&cfg, contrast_kernel, emb, pids, amask, targets, mask, out);
}

// round 13
// speedup vs baseline: 2.1332x; 1.4167x over previous
#include <cuda_runtime.h>
#include <math_constants.h>
#include <stdint.h>

#define NROWS 8192      // B*M
#define VSZ   5003
#define NB    64
#define SSEQ  200
#define DDIM  128
#define NNEG  4
#define MAXA  8
#define INV_TAU (1.0f/0.07f)
#define KS    32         // dims per k-slice
#define NSL   (DDIM/KS)  // 4 slices
#define NCON  (NB*NNEG)  // 256 contrast blocks
#define NRED  32         // fl-reduce blocks (256 rows each)
#define SGRID (NCON + NRED)
#define NEGSENT (-1e30f)

// deterministic scratch (single int counter atomic; no float atomics)
__device__ float g_fl[NROWS];
__device__ float g_pfl[NRED];
__device__ float g_pcnt[NRED];
__device__ int   g_na[NB];
__device__ float g_pm[NB][NNEG][MAXA];
__device__ float g_psum[NB][NNEG][MAXA];
__device__ float g_possim[NB][MAXA];
__device__ int   g_ctr = 0;          // last-block-done counter (self-resetting)

// packed fp32x2 FMA (sm_10x): d = a*b + d, two independent fp32 lanes
__device__ __forceinline__ void fma2(unsigned long long& d,
                                     unsigned long long a, unsigned long long b) {
    asm("fma.rn.f32x2 %0, %1, %2, %0;" : "+l"(d) : "l"(a), "l"(b));
}
__device__ __forceinline__ float2 unpack2(unsigned long long v) {
    float2 r; asm("mov.b64 {%0, %1}, %2;" : "=f"(r.x), "=f"(r.y) : "l"(v));
    return r;
}

// ================= focal (one-pass, no-max — measured best, UNCHANGED) =====
__global__ __launch_bounds__(256) void focal_kernel(
    const float* __restrict__ logits,
    const int*   __restrict__ targets,
    const int*   __restrict__ mask)
{
    int r = blockIdx.x;
    int tid = threadIdx.x, lane = tid & 31, w = tid >> 5;
    int t = targets[r];
    bool valid = (t != -100) && (mask[r] == 1);
    if (!valid) {
        if (tid == 0) g_fl[r] = 0.f;
        return;
    }
    const float* row = logits + (size_t)r * VSZ;
    float lt = __ldg(row + t);                               // target logit
    int pre = (4 - (int)(((uintptr_t)row >> 2) & 3)) & 3;    // peel to 16B align
    const float4* rv = (const float4*)(row + pre);
    int nv = (VSZ - pre) >> 2;
    int tail = pre + (nv << 2);

    float s = 0.f;
    if (tid < pre) s += __expf(row[tid]);
    for (int i = tid; i < nv; i += 256) {
        float4 x = rv[i];
        s += __expf(x.x) + __expf(x.y) + __expf(x.z) + __expf(x.w);
    }
    for (int i = tail + tid; i < VSZ; i += 256) s += __expf(row[i]);

    #pragma unroll
    for (int o = 16; o; o >>= 1) s += __shfl_xor_sync(0xffffffffu, s, o);
    __shared__ float ss[8];
    if (lane == 0) ss[w] = s;
    __syncthreads();
    if (tid == 0) {
        float S = 0.f;
        #pragma unroll
        for (int i = 0; i < 8; i++) S += ss[i];
        float lp = lt - logf(S);          // log p_t
        float pt = __expf(lp);
        float om = 1.f - pt;
        g_fl[r] = om * om * (-lp);
    }
}

// ======= contrast V2 (blocks 0..255) + fl-reduce (256..287) + finalize =====
struct ConSmem {
    float anch[MAXA][DDIM];          // normalized anchors         4 KB
    float tile[SSEQ][KS + 4];        // raw negative k-slice      28.8 KB
    float sims[SSEQ][MAXA + 1];      // sim[neg][anchor], padded   7.2 KB
    unsigned bal[8];
    int sel[16];
    int na;
    unsigned char nv[SSEQ];
};

__global__ __launch_bounds__(256) void contrast_kernel(
    const float* __restrict__ emb,
    const int*   __restrict__ pids,
    const int*   __restrict__ amask,
    const int*   __restrict__ targets,
    const int*   __restrict__ mask,
    float* __restrict__ out)
{
    __shared__ __align__(16) char sm_raw[sizeof(ConSmem)];
    int tid = threadIdx.x, lane = tid & 31, w = tid >> 5;
    int blk = blockIdx.x;

    if (blk >= NCON) {
        // ---- fl partial reduction (focal finished: same stream) ----
        int k = blk - NCON;
        int r = k * 256 + tid;
        float f = g_fl[r];
        int tt = targets[r];
        float c = ((tt != -100) && (mask[r] == 1)) ? 1.f : 0.f;
        #pragma unroll
        for (int o = 16; o; o >>= 1) {
            f += __shfl_xor_sync(0xffffffffu, f, o);
            c += __shfl_xor_sync(0xffffffffu, c, o);
        }
        float* sf = (float*)sm_raw;
        float* sc = sf + 8;
        if (lane == 0) { sf[w] = f; sc[w] = c; }
        __syncthreads();
        if (tid == 0) {
            float F = 0.f, C = 0.f;
            #pragma unroll
            for (int i = 0; i < 8; i++) { F += sf[i]; C += sc[i]; }
            g_pfl[k] = F; g_pcnt[k] = C;
        }
    } else {
        ConSmem* S = (ConSmem*)sm_raw;
        int b = blk >> 2, j = blk & 3;
        int nb = j + (j >= b ? 1 : 0);       // others[b][j]

        // validity (own via ballot, neighbor via bytes)
        bool myv = false;
        if (tid < SSEQ) {
            myv = (amask[b * SSEQ + tid] == 1 && pids[b * SSEQ + tid] > 0);
            S->nv[tid] = (amask[nb * SSEQ + tid] == 1 && pids[nb * SSEQ + tid] > 0) ? 1 : 0;
        }
        unsigned bal = __ballot_sync(0xffffffffu, myv);
        if (lane == 0) S->bal[w] = bal;      // warps 0..6 carry bits, 7 is zero
        __syncthreads();
        if (tid == 0) {
            int n = 0;
            #pragma unroll
            for (int wd = 0; wd < 7; wd++) n += __popc(S->bal[wd]);
            int na = n / 2; if (na > MAXA) na = MAXA;
            S->na = na;
            int first16[16];
            #pragma unroll
            for (int i = 0; i < 16; i++) first16[i] = 0;
            int cnt = 0;
            for (int wd = 0; wd < 7 && cnt < 16; wd++) {
                unsigned bb = S->bal[wd];
                while (bb && cnt < 16) {
                    int p = __ffs(bb) - 1;
                    first16[cnt++] = wd * 32 + p;
                    bb &= bb - 1;
                }
            }
            #pragma unroll
            for (int i = 0; i < 16; i++) S->sel[i] = first16[i];
        }
        __syncthreads();
        int na = S->na;

        // warp w: load + normalize anchor w
        {
            int ai = S->sel[w];
            float4 a4 = ((const float4*)(emb + ((size_t)b * SSEQ + ai) * DDIM))[lane];
            float n2 = a4.x * a4.x + a4.y * a4.y + a4.z * a4.z + a4.w * a4.w;
            #pragma unroll
            for (int o = 16; o; o >>= 1) n2 += __shfl_xor_sync(0xffffffffu, n2, o);
            float inv = 1.0f / fmaxf(sqrtf(n2), 1e-12f);
            a4.x *= inv; a4.y *= inv; a4.z *= inv; a4.w *= inv;
            ((float4*)S->anch[w])[lane] = a4;
        }

        // positive similarity (j==0): warp w -> anchor w (own-warp anch)
        if (j == 0 && w < na) {
            int pi = S->sel[na + w];
            float4 p = ((const float4*)(emb + ((size_t)b * SSEQ + pi) * DDIM))[lane];
            float4 a4 = ((const float4*)S->anch[w])[lane];
            float d  = a4.x * p.x + a4.y * p.y + a4.z * p.z + a4.w * p.w;
            float pn = p.x * p.x + p.y * p.y + p.z * p.z + p.w * p.w;
            #pragma unroll
            for (int o = 16; o; o >>= 1) {
                d  += __shfl_xor_sync(0xffffffffu, d,  o);
                pn += __shfl_xor_sync(0xffffffffu, pn, o);
            }
            if (lane == 0)
                g_possim[b][w] = d * (1.0f / fmaxf(sqrtf(pn), 1e-12f)) * INV_TAU;
        }

        // negatives: thread = negative; packed f32x2 dot vs all 8 anchors
        const float* nbase = emb + (size_t)nb * SSEQ * DDIM;
        int nc = (tid < SSEQ) ? tid : (SSEQ - 1);
        unsigned long long acc2[MAXA], nnacc = 0ULL;
        #pragma unroll
        for (int a = 0; a < MAXA; a++) acc2[a] = 0ULL;

        for (int sl = 0; sl < NSL; sl++) {
            __syncthreads();                 // prev slice consumed / anchors ready
            for (int q = tid; q < SSEQ * 8; q += 256) {
                int rowi = q >> 3, col = q & 7;
                *(float4*)&S->tile[rowi][col * 4] =
                    ((const float4*)(nbase + (size_t)rowi * DDIM + sl * KS))[col];
            }
            __syncthreads();
            const ulonglong2* tr = (const ulonglong2*)&S->tile[nc][0];
            #pragma unroll
            for (int c = 0; c < 8; c++) {
                ulonglong2 ng = tr[c];                        // conflict-free
                fma2(nnacc, ng.x, ng.x);
                fma2(nnacc, ng.y, ng.y);
                #pragma unroll
                for (int a = 0; a < MAXA; a++) {
                    ulonglong2 av =
                        *(const ulonglong2*)&S->anch[a][sl * KS + c * 4]; // broadcast
                    fma2(acc2[a], av.x, ng.x);
                    fma2(acc2[a], av.y, ng.y);
                }
            }
        }

        // write sims (NEGSENT for invalid) into padded smem
        float2 nf = unpack2(nnacc);
        float sc2 = (1.0f / fmaxf(sqrtf(nf.x + nf.y), 1e-12f)) * INV_TAU;
        bool vld = (tid < SSEQ) && S->nv[tid];
        if (tid < SSEQ) {
            #pragma unroll
            for (int a = 0; a < MAXA; a++) {
                float2 d2 = unpack2(acc2[a]);
                S->sims[tid][a] = vld ? (d2.x + d2.y) * sc2 : NEGSENT;
            }
        }
        __syncthreads();

        // transposed epilogue: warp w reduces anchor w over 200 negatives
        {
            float vals[7];
            float mv = NEGSENT;
            #pragma unroll
            for (int k = 0; k < 7; k++) {
                int n = lane + 32 * k;
                vals[k] = (n < SSEQ) ? S->sims[n][w] : NEGSENT;  // stride 9: no conflicts
                mv = fmaxf(mv, vals[k]);
            }
            #pragma unroll
            for (int o = 16; o; o >>= 1) mv = fmaxf(mv, __shfl_xor_sync(0xffffffffu, mv, o));
            float e = 0.f;
            #pragma unroll
            for (int k = 0; k < 7; k++) e += __expf(vals[k] - mv);
            #pragma unroll
            for (int o = 16; o; o >>= 1) e += __shfl_xor_sync(0xffffffffu, e, o);
            if (lane == 0) { g_pm[b][j][w] = mv; g_psum[b][j][w] = e; }
        }
        if (j == 0 && tid == 0) g_na[b] = na;
    }

    // ================= last-block-done finalize (deterministic) ============
    __threadfence();
    __shared__ int s_last;
    if (tid == 0) {
        int vdone = atomicAdd(&g_ctr, 1);
        s_last = (vdone == SGRID - 1) ? 1 : 0;
    }
    __syncthreads();
    if (!s_last) return;

    float fs  = (tid < NRED) ? g_pfl[tid]  : 0.f;
    float cnt = (tid < NRED) ? g_pcnt[tid] : 0.f;

    float closs = 0.f;
    #pragma unroll
    for (int rep = 0; rep < 2; rep++) {
        int idx = tid + rep * 256;
        int b = idx >> 3, aq = idx & 7;
        int na = g_na[b];
        float ps = g_possim[b][aq];
        float m = ps, ssum = 1.f;
        #pragma unroll
        for (int jj = 0; jj < NNEG; jj++) {
            float pm  = g_pm[b][jj][aq];
            float pss = g_psum[b][jj][aq];
            if (pss > 0.f) {
                float nm = fmaxf(m, pm);
                ssum = ssum * __expf(m - nm) + pss * __expf(pm - nm);
                m = nm;
            }
        }
        closs += (aq < na) ? ((m + logf(ssum)) - ps) : 0.f;
    }
    float pairs = (tid < NB) ? (float)g_na[tid] : 0.f;

    int lane2 = tid & 31, w2 = tid >> 5;
    #pragma unroll
    for (int o = 16; o; o >>= 1) {
        fs    += __shfl_xor_sync(0xffffffffu, fs,    o);
        cnt   += __shfl_xor_sync(0xffffffffu, cnt,   o);
        closs += __shfl_xor_sync(0xffffffffu, closs, o);
        pairs += __shfl_xor_sync(0xffffffffu, pairs, o);
    }
    __shared__ float4 sred[8];
    if (lane2 == 0) sred[w2] = make_float4(fs, cnt, closs, pairs);
    __syncthreads();
    if (tid == 0) {
        float F = 0.f, C = 0.f, L = 0.f, P = 0.f;
        #pragma unroll
        for (int i = 0; i < 8; i++) {
            float4 q = sred[i];
            F += q.x; C += q.y; L += q.z; P += q.w;
        }
        float focal = C > 0.f ? F / C : 0.f;
        float contr = P > 0.f ? L / P : 0.f;
        out[0] = 0.6f * focal + 0.2f * contr;
        g_ctr = 0;                           // reset for next graph replay
    }
}

extern "C" void kernel_launch(void* const* d_in, const int* in_sizes, int n_in,
                              void* d_out, int out_size)
{
    const float* logits  = (const float*)d_in[0];
    const int*   targets = (const int*)d_in[1];
    const int*   mask    = (const int*)d_in[2];
    const float* emb     = (const float*)d_in[3];
    const int*   pids    = (const int*)d_in[4];
    const int*   amask   = (const int*)d_in[5];
    float* out = (float*)d_out;

    focal_kernel<<<NROWS, 256>>>(logits, targets, mask);
    contrast_kernel<<<SGRID, 256>>>(emb, pids, amask, targets, mask, out);
}

// round 14
// speedup vs baseline: 2.2502x; 1.0548x over previous
#include <cuda_runtime.h>
#include <math_constants.h>
#include <stdint.h>

#define NROWS 8192      // B*M
#define VSZ   5003
#define NB    64
#define SSEQ  200
#define DDIM  128
#define NNEG  4
#define MAXA  8
#define INV_TAU (1.0f/0.07f)
#define KS    32         // dims per k-slice
#define NSL   (DDIM/KS)  // 4 slices
#define NCON  (NB*NNEG)  // 256 contrast blocks
#define NRED  32         // fl-reduce blocks (256 rows each)
#define SGRID (NCON + NRED)
#define NEGSENT (-1e30f)

// deterministic scratch (single int counter atomic; no float atomics)
__device__ float g_fl[NROWS];
__device__ float g_pfl[NRED];
__device__ float g_pcnt[NRED];
__device__ int   g_na[NB];
__device__ float g_pm[NB][NNEG][MAXA];
__device__ float g_psum[NB][NNEG][MAXA];
__device__ float g_possim[NB][MAXA];
__device__ int   g_ctr = 0;          // last-block-done counter (self-resetting)

// packed fp32x2 FMA (sm_10x): d = a*b + d, two independent fp32 lanes
__device__ __forceinline__ void fma2(unsigned long long& d,
                                     unsigned long long a, unsigned long long b) {
    asm("fma.rn.f32x2 %0, %1, %2, %0;" : "+l"(d) : "l"(a), "l"(b));
}
__device__ __forceinline__ float2 unpack2(unsigned long long v) {
    float2 r; asm("mov.b64 {%0, %1}, %2;" : "=f"(r.x), "=f"(r.y) : "l"(v));
    return r;
}

// ========== focal: TWO rows per block (4 warps each), one-pass no-max ======
__global__ __launch_bounds__(256) void focal_kernel(
    const float* __restrict__ logits,
    const int*   __restrict__ targets,
    const int*   __restrict__ mask)
{
    int tid = threadIdx.x, lane = tid & 31, w = tid >> 5;
    int half = w >> 2;                   // 0: warps 0-3, 1: warps 4-7
    int ht   = tid & 127;                // thread index within half
    int r = blockIdx.x * 2 + half;

    int t = targets[r];
    bool valid = (t != -100) && (mask[r] == 1);
    const float* row = logits + (size_t)r * VSZ;
    float lt = valid ? __ldg(row + t) : 0.f;
    int pre = (4 - (int)(((uintptr_t)row >> 2) & 3)) & 3;    // peel to 16B align
    const float4* rv = (const float4*)(row + pre);
    int nvfull = (VSZ - pre) >> 2;
    int tail = pre + (nvfull << 2);
    int nv = valid ? nvfull : 0;         // invalid half: skip loop, keep barriers

    float s = 0.f;
    if (valid && ht < pre) s += __expf(row[ht]);
    for (int i = ht; i < nv; i += 128) {
        float4 x = rv[i];
        s += __expf(x.x) + __expf(x.y) + __expf(x.z) + __expf(x.w);
    }
    if (valid)
        for (int i = tail + ht; i < VSZ; i += 128) s += __expf(row[i]);

    #pragma unroll
    for (int o = 16; o; o >>= 1) s += __shfl_xor_sync(0xffffffffu, s, o);
    __shared__ float ss[8];
    if (lane == 0) ss[w] = s;
    __syncthreads();
    if (ht == 0) {                       // tid 0 (half 0) and tid 128 (half 1)
        if (!valid) {
            g_fl[r] = 0.f;
        } else {
            int base = half * 4;
            float S = (ss[base] + ss[base + 1]) + (ss[base + 2] + ss[base + 3]);
            float lp = lt - logf(S);     // log p_t
            float pt = __expf(lp);
            float om = 1.f - pt;
            g_fl[r] = om * om * (-lp);
        }
    }
}

// ======= contrast V2 (blocks 0..255) + fl-reduce (256..287) + finalize =====
// (unchanged from the 39.4us build)
struct ConSmem {
    float anch[MAXA][DDIM];          // normalized anchors         4 KB
    float tile[SSEQ][KS + 4];        // raw negative k-slice      28.8 KB
    float sims[SSEQ][MAXA + 1];      // sim[neg][anchor], padded   7.2 KB
    unsigned bal[8];
    int sel[16];
    int na;
    unsigned char nv[SSEQ];
};

__global__ __launch_bounds__(256) void contrast_kernel(
    const float* __restrict__ emb,
    const int*   __restrict__ pids,
    const int*   __restrict__ amask,
    const int*   __restrict__ targets,
    const int*   __restrict__ mask,
    float* __restrict__ out)
{
    __shared__ __align__(16) char sm_raw[sizeof(ConSmem)];
    int tid = threadIdx.x, lane = tid & 31, w = tid >> 5;
    int blk = blockIdx.x;

    if (blk >= NCON) {
        // ---- fl partial reduction (focal finished: same stream) ----
        int k = blk - NCON;
        int r = k * 256 + tid;
        float f = g_fl[r];
        int tt = targets[r];
        float c = ((tt != -100) && (mask[r] == 1)) ? 1.f : 0.f;
        #pragma unroll
        for (int o = 16; o; o >>= 1) {
            f += __shfl_xor_sync(0xffffffffu, f, o);
            c += __shfl_xor_sync(0xffffffffu, c, o);
        }
        float* sf = (float*)sm_raw;
        float* sc = sf + 8;
        if (lane == 0) { sf[w] = f; sc[w] = c; }
        __syncthreads();
        if (tid == 0) {
            float F = 0.f, C = 0.f;
            #pragma unroll
            for (int i = 0; i < 8; i++) { F += sf[i]; C += sc[i]; }
            g_pfl[k] = F; g_pcnt[k] = C;
        }
    } else {
        ConSmem* S = (ConSmem*)sm_raw;
        int b = blk >> 2, j = blk & 3;
        int nb = j + (j >= b ? 1 : 0);       // others[b][j]

        bool myv = false;
        if (tid < SSEQ) {
            myv = (amask[b * SSEQ + tid] == 1 && pids[b * SSEQ + tid] > 0);
            S->nv[tid] = (amask[nb * SSEQ + tid] == 1 && pids[nb * SSEQ + tid] > 0) ? 1 : 0;
        }
        unsigned bal = __ballot_sync(0xffffffffu, myv);
        if (lane == 0) S->bal[w] = bal;
        __syncthreads();
        if (tid == 0) {
            int n = 0;
            #pragma unroll
            for (int wd = 0; wd < 7; wd++) n += __popc(S->bal[wd]);
            int na = n / 2; if (na > MAXA) na = MAXA;
            S->na = na;
            int first16[16];
            #pragma unroll
            for (int i = 0; i < 16; i++) first16[i] = 0;
            int cnt = 0;
            for (int wd = 0; wd < 7 && cnt < 16; wd++) {
                unsigned bb = S->bal[wd];
                while (bb && cnt < 16) {
                    int p = __ffs(bb) - 1;
                    first16[cnt++] = wd * 32 + p;
                    bb &= bb - 1;
                }
            }
            #pragma unroll
            for (int i = 0; i < 16; i++) S->sel[i] = first16[i];
        }
        __syncthreads();
        int na = S->na;

        {
            int ai = S->sel[w];
            float4 a4 = ((const float4*)(emb + ((size_t)b * SSEQ + ai) * DDIM))[lane];
            float n2 = a4.x * a4.x + a4.y * a4.y + a4.z * a4.z + a4.w * a4.w;
            #pragma unroll
            for (int o = 16; o; o >>= 1) n2 += __shfl_xor_sync(0xffffffffu, n2, o);
            float inv = 1.0f / fmaxf(sqrtf(n2), 1e-12f);
            a4.x *= inv; a4.y *= inv; a4.z *= inv; a4.w *= inv;
            ((float4*)S->anch[w])[lane] = a4;
        }

        if (j == 0 && w < na) {
            int pi = S->sel[na + w];
            float4 p = ((const float4*)(emb + ((size_t)b * SSEQ + pi) * DDIM))[lane];
            float4 a4 = ((const float4*)S->anch[w])[lane];
            float d  = a4.x * p.x + a4.y * p.y + a4.z * p.z + a4.w * p.w;
            float pn = p.x * p.x + p.y * p.y + p.z * p.z + p.w * p.w;
            #pragma unroll
            for (int o = 16; o; o >>= 1) {
                d  += __shfl_xor_sync(0xffffffffu, d,  o);
                pn += __shfl_xor_sync(0xffffffffu, pn, o);
            }
            if (lane == 0)
                g_possim[b][w] = d * (1.0f / fmaxf(sqrtf(pn), 1e-12f)) * INV_TAU;
        }

        const float* nbase = emb + (size_t)nb * SSEQ * DDIM;
        int nc = (tid < SSEQ) ? tid : (SSEQ - 1);
        unsigned long long acc2[MAXA], nnacc = 0ULL;
        #pragma unroll
        for (int a = 0; a < MAXA; a++) acc2[a] = 0ULL;

        for (int sl = 0; sl < NSL; sl++) {
            __syncthreads();
            for (int q = tid; q < SSEQ * 8; q += 256) {
                int rowi = q >> 3, col = q & 7;
                *(float4*)&S->tile[rowi][col * 4] =
                    ((const float4*)(nbase + (size_t)rowi * DDIM + sl * KS))[col];
            }
            __syncthreads();
            const ulonglong2* tr = (const ulonglong2*)&S->tile[nc][0];
            #pragma unroll
            for (int c = 0; c < 8; c++) {
                ulonglong2 ng = tr[c];
                fma2(nnacc, ng.x, ng.x);
                fma2(nnacc, ng.y, ng.y);
                #pragma unroll
                for (int a = 0; a < MAXA; a++) {
                    ulonglong2 av =
                        *(const ulonglong2*)&S->anch[a][sl * KS + c * 4];
                    fma2(acc2[a], av.x, ng.x);
                    fma2(acc2[a], av.y, ng.y);
                }
            }
        }

        float2 nf = unpack2(nnacc);
        float sc2 = (1.0f / fmaxf(sqrtf(nf.x + nf.y), 1e-12f)) * INV_TAU;
        bool vld = (tid < SSEQ) && S->nv[tid];
        if (tid < SSEQ) {
            #pragma unroll
            for (int a = 0; a < MAXA; a++) {
                float2 d2 = unpack2(acc2[a]);
                S->sims[tid][a] = vld ? (d2.x + d2.y) * sc2 : NEGSENT;
            }
        }
        __syncthreads();

        {
            float vals[7];
            float mv = NEGSENT;
            #pragma unroll
            for (int k = 0; k < 7; k++) {
                int n = lane + 32 * k;
                vals[k] = (n < SSEQ) ? S->sims[n][w] : NEGSENT;
                mv = fmaxf(mv, vals[k]);
            }
            #pragma unroll
            for (int o = 16; o; o >>= 1) mv = fmaxf(mv, __shfl_xor_sync(0xffffffffu, mv, o));
            float e = 0.f;
            #pragma unroll
            for (int k = 0; k < 7; k++) e += __expf(vals[k] - mv);
            #pragma unroll
            for (int o = 16; o; o >>= 1) e += __shfl_xor_sync(0xffffffffu, e, o);
            if (lane == 0) { g_pm[b][j][w] = mv; g_psum[b][j][w] = e; }
        }
        if (j == 0 && tid == 0) g_na[b] = na;
    }

    // ================= last-block-done finalize (deterministic) ============
    __threadfence();
    __shared__ int s_last;
    if (tid == 0) {
        int vdone = atomicAdd(&g_ctr, 1);
        s_last = (vdone == SGRID - 1) ? 1 : 0;
    }
    __syncthreads();
    if (!s_last) return;

    float fs  = (tid < NRED) ? g_pfl[tid]  : 0.f;
    float cnt = (tid < NRED) ? g_pcnt[tid] : 0.f;

    float closs = 0.f;
    #pragma unroll
    for (int rep = 0; rep < 2; rep++) {
        int idx = tid + rep * 256;
        int b = idx >> 3, aq = idx & 7;
        int na = g_na[b];
        float ps = g_possim[b][aq];
        float m = ps, ssum = 1.f;
        #pragma unroll
        for (int jj = 0; jj < NNEG; jj++) {
            float pm  = g_pm[b][jj][aq];
            float pss = g_psum[b][jj][aq];
            if (pss > 0.f) {
                float nm = fmaxf(m, pm);
                ssum = ssum * __expf(m - nm) + pss * __expf(pm - nm);
                m = nm;
            }
        }
        closs += (aq < na) ? ((m + logf(ssum)) - ps) : 0.f;
    }
    float pairs = (tid < NB) ? (float)g_na[tid] : 0.f;

    int lane2 = tid & 31, w2 = tid >> 5;
    #pragma unroll
    for (int o = 16; o; o >>= 1) {
        fs    += __shfl_xor_sync(0xffffffffu, fs,    o);
        cnt   += __shfl_xor_sync(0xffffffffu, cnt,   o);
        closs += __shfl_xor_sync(0xffffffffu, closs, o);
        pairs += __shfl_xor_sync(0xffffffffu, pairs, o);
    }
    __shared__ float4 sred[8];
    if (lane2 == 0) sred[w2] = make_float4(fs, cnt, closs, pairs);
    __syncthreads();
    if (tid == 0) {
        float F = 0.f, C = 0.f, L = 0.f, P = 0.f;
        #pragma unroll
        for (int i = 0; i < 8; i++) {
            float4 q = sred[i];
            F += q.x; C += q.y; L += q.z; P += q.w;
        }
        float focal = C > 0.f ? F / C : 0.f;
        float contr = P > 0.f ? L / P : 0.f;
        out[0] = 0.6f * focal + 0.2f * contr;
        g_ctr = 0;                           // reset for next graph replay
    }
}

extern "C" void kernel_launch(void* const* d_in, const int* in_sizes, int n_in,
                              void* d_out, int out_size)
{
    const float* logits  = (const float*)d_in[0];
    const int*   targets = (const int*)d_in[1];
    const int*   mask    = (const int*)d_in[2];
    const float* emb     = (const float*)d_in[3];
    const int*   pids    = (const int*)d_in[4];
    const int*   amask   = (const int*)d_in[5];
    float* out = (float*)d_out;

    focal_kernel<<<NROWS / 2, 256>>>(logits, targets, mask);
    contrast_kernel<<<SGRID, 256>>>(emb, pids, amask, targets, mask, out);
}